// round 5
// baseline (speedup 1.0000x reference)
#include <cuda_runtime.h>
#include <math.h>

// ---------------------------------------------------------------------------
// GPT-2 forward, fp32. B=8 T=512 E=1024 H=16 D=64 F=4096 V=512 L=12
// Round 4: double-buffered / register-prefetch GEMM mainloop.
// ---------------------------------------------------------------------------

#define EE   1024
#define TT   512
#define BB   8
#define VV   512
#define LL   12
#define FF   4096
#define MR   4096           // B*T rows
#define HH   16
#define DD   64

// Scratch (device globals: allocation-free rule)
__device__ float g_h  [(size_t)MR * EE];
__device__ float g_xn [(size_t)MR * EE];
__device__ float g_q  [(size_t)MR * EE];
__device__ float g_k  [(size_t)MR * EE];
__device__ float g_v  [(size_t)MR * EE];
__device__ float g_y  [(size_t)MR * EE];
__device__ float g_mlp[(size_t)MR * FF];

// ---------------------------------------------------------------------------
// Embedding: h[b*T+t] = tok_emb[x[b,t]] + pos_emb[t]
// ---------------------------------------------------------------------------
__global__ void embed_kernel(const int* __restrict__ x,
                             const float* __restrict__ tok,
                             const float* __restrict__ pos,
                             float* __restrict__ h)
{
    int row = blockIdx.x;               // 0..4095
    int t   = row & (TT - 1);
    int tk  = x[row];
    const float* te = tok + (size_t)tk * EE;
    const float* pe = pos + (size_t)t  * EE;
    float* hr = h + (size_t)row * EE;
    for (int j = threadIdx.x; j < EE; j += blockDim.x)
        hr[j] = te[j] + pe[j];
}

// ---------------------------------------------------------------------------
// LayerNorm: out = (x - mu) * rsqrt(var + 1e-5) * g + b   (one block per row)
// ---------------------------------------------------------------------------
__global__ void ln_kernel(const float* __restrict__ x,
                          const float* __restrict__ g,
                          const float* __restrict__ b,
                          float* __restrict__ out)
{
    int row = blockIdx.x;
    const float* xr = x + (size_t)row * EE;
    float s = 0.f, s2 = 0.f;
    for (int j = threadIdx.x; j < EE; j += 256) {
        float v = xr[j];
        s += v; s2 += v * v;
    }
    #pragma unroll
    for (int o = 16; o; o >>= 1) {
        s  += __shfl_xor_sync(0xffffffffu, s,  o);
        s2 += __shfl_xor_sync(0xffffffffu, s2, o);
    }
    __shared__ float sh[2][8];
    int w = threadIdx.x >> 5, lane = threadIdx.x & 31;
    if (lane == 0) { sh[0][w] = s; sh[1][w] = s2; }
    __syncthreads();
    if (w == 0) {
        s  = (lane < 8) ? sh[0][lane] : 0.f;
        s2 = (lane < 8) ? sh[1][lane] : 0.f;
        #pragma unroll
        for (int o = 4; o; o >>= 1) {
            s  += __shfl_xor_sync(0xffffffffu, s,  o);
            s2 += __shfl_xor_sync(0xffffffffu, s2, o);
        }
        if (lane == 0) { sh[0][0] = s; sh[1][0] = s2; }
    }
    __syncthreads();
    s = sh[0][0]; s2 = sh[1][0];
    float mu  = s * (1.f / EE);
    float var = s2 * (1.f / EE) - mu * mu;
    float rs  = rsqrtf(var + 1e-5f);
    float* orow = out + (size_t)row * EE;
    for (int j = threadIdx.x; j < 256 * ((EE + 255) / 256); j += 256)
        if (j < EE)
            orow[j] = (xr[j] - mu) * rs * g[j] + b[j];
}

// ---------------------------------------------------------------------------
// GEMM: C = act(A[M,K] @ W[K,N] + bias) + res
//   act: 0 = none, 1 = exact GELU. bias/res may be null.
//   128x128x8 tile, 256 threads, 8x8 per-thread microkernel.
//   Double-buffered smem + register prefetch (1 barrier per k-tile).
//   Requires M%128==0, N%128==0, K%8==0 (all shapes here comply).
// ---------------------------------------------------------------------------
#define GBM 128
#define GBN 128
#define GBK 8
#define GTM 8
#define GTN 8

__global__ __launch_bounds__(256)
void gemm_kernel(const float* __restrict__ A, const float* __restrict__ W,
                 const float* __restrict__ bias, const float* __restrict__ res,
                 float* __restrict__ C, int M, int N, int K, int act)
{
    __shared__ float As[2][GBK][GBM];
    __shared__ float Bs[2][GBK][GBN];

    int tid  = threadIdx.x;
    int row0 = blockIdx.y * GBM;
    int col0 = blockIdx.x * GBN;

    int aRow  = tid >> 1;             // 0..127
    int aCol4 = (tid & 1) * 4;        // 0 or 4
    int bRow  = tid >> 5;             // 0..7
    int bCol4 = (tid & 31) * 4;       // 0..124

    int tr = (tid >> 4) * GTM;        // 0..120 step 8
    int tc = (tid & 15) * GTN;        // 0..120 step 8

    float acc[GTM][GTN];
    #pragma unroll
    for (int i = 0; i < GTM; i++)
        #pragma unroll
        for (int j = 0; j < GTN; j++) acc[i][j] = 0.f;

    const float* aPtr = A + (size_t)(row0 + aRow) * K + aCol4;
    const float* bPtr = W + (size_t)bRow * N + col0 + bCol4;

    // --- prologue: load k-tile 0 into buffer 0 ---
    {
        float4 av = *(const float4*)(aPtr);
        As[0][aCol4 + 0][aRow] = av.x;
        As[0][aCol4 + 1][aRow] = av.y;
        As[0][aCol4 + 2][aRow] = av.z;
        As[0][aCol4 + 3][aRow] = av.w;
        float4 bv = *(const float4*)(bPtr);
        *(float4*)&Bs[0][bRow][bCol4] = bv;
    }
    __syncthreads();

    int buf = 0;
    for (int k0 = GBK; k0 < K; k0 += GBK) {
        // prefetch next k-tile into registers (overlaps with compute below)
        float4 avN = *(const float4*)(aPtr + k0);
        float4 bvN = *(const float4*)(bPtr + (size_t)k0 * N);

        // compute current buffer
        #pragma unroll
        for (int kk = 0; kk < GBK; ++kk) {
            float a[GTM], b[GTN];
            float4 a0 = *(const float4*)&As[buf][kk][tr];
            float4 a1 = *(const float4*)&As[buf][kk][tr + 4];
            a[0]=a0.x; a[1]=a0.y; a[2]=a0.z; a[3]=a0.w;
            a[4]=a1.x; a[5]=a1.y; a[6]=a1.z; a[7]=a1.w;
            float4 b0 = *(const float4*)&Bs[buf][kk][tc];
            float4 b1 = *(const float4*)&Bs[buf][kk][tc + 4];
            b[0]=b0.x; b[1]=b0.y; b[2]=b0.z; b[3]=b0.w;
            b[4]=b1.x; b[5]=b1.y; b[6]=b1.z; b[7]=b1.w;
            #pragma unroll
            for (int i = 0; i < GTM; i++)
                #pragma unroll
                for (int j = 0; j < GTN; j++)
                    acc[i][j] = fmaf(a[i], b[j], acc[i][j]);
        }

        // store prefetched tile into the other buffer
        int nb = buf ^ 1;
        As[nb][aCol4 + 0][aRow] = avN.x;
        As[nb][aCol4 + 1][aRow] = avN.y;
        As[nb][aCol4 + 2][aRow] = avN.z;
        As[nb][aCol4 + 3][aRow] = avN.w;
        *(float4*)&Bs[nb][bRow][bCol4] = bvN;
        __syncthreads();
        buf = nb;
    }

    // --- epilogue compute on the last buffer ---
    #pragma unroll
    for (int kk = 0; kk < GBK; ++kk) {
        float a[GTM], b[GTN];
        float4 a0 = *(const float4*)&As[buf][kk][tr];
        float4 a1 = *(const float4*)&As[buf][kk][tr + 4];
        a[0]=a0.x; a[1]=a0.y; a[2]=a0.z; a[3]=a0.w;
        a[4]=a1.x; a[5]=a1.y; a[6]=a1.z; a[7]=a1.w;
        float4 b0 = *(const float4*)&Bs[buf][kk][tc];
        float4 b1 = *(const float4*)&Bs[buf][kk][tc + 4];
        b[0]=b0.x; b[1]=b0.y; b[2]=b0.z; b[3]=b0.w;
        b[4]=b1.x; b[5]=b1.y; b[6]=b1.z; b[7]=b1.w;
        #pragma unroll
        for (int i = 0; i < GTM; i++)
            #pragma unroll
            for (int j = 0; j < GTN; j++)
                acc[i][j] = fmaf(a[i], b[j], acc[i][j]);
    }

    #pragma unroll
    for (int i = 0; i < GTM; i++) {
        size_t r = (size_t)(row0 + tr + i) * N;
        #pragma unroll
        for (int j = 0; j < GTN; j++) {
            int c = col0 + tc + j;
            float v = acc[i][j];
            if (bias) v += bias[c];
            if (act == 1) v = 0.5f * v * (1.f + erff(v * 0.70710678118654752f));
            if (res)  v += res[r + c];
            C[r + c] = v;
        }
    }
}

// ---------------------------------------------------------------------------
// Attention: per (b, head, 8-query tile). Exact two-pass softmax with causal
// mask. Scores kept in smem; K loaded transposed for conflict-free dots.
// ---------------------------------------------------------------------------
#define AQ 8

__global__ __launch_bounds__(256)
void attn_kernel(const float* __restrict__ q, const float* __restrict__ k,
                 const float* __restrict__ v, float* __restrict__ y)
{
    int qt = blockIdx.x & 63;          // query tile (64 tiles of 8)
    int bh = blockIdx.x >> 6;
    int h_ = bh & (HH - 1);
    int b  = bh >> 4;
    int q0 = qt * AQ;
    size_t baseRow = (size_t)b * TT;
    int colOff = h_ * DD;

    __shared__ float Qs[AQ][DD];
    __shared__ float S [AQ][TT];
    __shared__ float Tl[DD][68];       // K^T in phase 1, V in phase 3 (row pad)

    int tid  = threadIdx.x;
    int lane = tid & 31;
    int wq   = tid >> 5;               // warp id == query index (8 warps)
    const float scale = 0.125f;        // 1/sqrt(64)

    for (int idx = tid; idx < AQ * DD; idx += 256) {
        int qi = idx >> 6, d = idx & 63;
        Qs[qi][d] = q[(baseRow + q0 + qi) * EE + colOff + d] * scale;
    }

    int qmaxg  = q0 + AQ - 1;
    int ntiles = (qmaxg >> 6) + 1;     // key tiles of 64 needed (causal)

    // ---- Phase 1: scores = Q K^T (masked) ----
    for (int kt = 0; kt < ntiles; ++kt) {
        int k0 = kt * 64;
        __syncthreads();               // Qs ready / previous Tl readers done
        for (int f = tid; f < 64 * 16; f += 256) {   // 1024 float4 loads
            int kk = f >> 4, c4 = (f & 15) * 4;
            float4 kv = *(const float4*)(k + (baseRow + k0 + kk) * EE + colOff + c4);
            Tl[c4 + 0][kk] = kv.x;
            Tl[c4 + 1][kk] = kv.y;
            Tl[c4 + 2][kk] = kv.z;
            Tl[c4 + 3][kk] = kv.w;
        }
        __syncthreads();
        float s0 = 0.f, s1 = 0.f;
        #pragma unroll 16
        for (int d = 0; d < DD; ++d) {
            float qv = Qs[wq][d];
            s0 = fmaf(qv, Tl[d][lane],      s0);
            s1 = fmaf(qv, Tl[d][lane + 32], s1);
        }
        int qg = q0 + wq;
        S[wq][k0 + lane]      = (k0 + lane      <= qg) ? s0 : -INFINITY;
        S[wq][k0 + lane + 32] = (k0 + lane + 32 <= qg) ? s1 : -INFINITY;
    }
    __syncthreads();

    // ---- Phase 2: softmax per row (warp wq owns row wq) ----
    {
        int kmaxb = ntiles * 64;
        float m = -INFINITY;
        for (int kk = lane; kk < kmaxb; kk += 32) m = fmaxf(m, S[wq][kk]);
        #pragma unroll
        for (int o = 16; o; o >>= 1) m = fmaxf(m, __shfl_xor_sync(0xffffffffu, m, o));
        float sum = 0.f;
        for (int kk = lane; kk < kmaxb; kk += 32) {
            float e = __expf(S[wq][kk] - m);
            S[wq][kk] = e;
            sum += e;
        }
        #pragma unroll
        for (int o = 16; o; o >>= 1) sum += __shfl_xor_sync(0xffffffffu, sum, o);
        float inv = 1.f / sum;
        for (int kk = lane; kk < kmaxb; kk += 32) S[wq][kk] *= inv;
    }
    __syncthreads();

    // ---- Phase 3: y = P @ V  (thread owns (row wq, dims lane & lane+32)) ----
    float y0 = 0.f, y1 = 0.f;
    for (int kt = 0; kt < ntiles; ++kt) {
        int k0 = kt * 64;
        for (int f = tid; f < 64 * 16; f += 256) {
            int kk = f >> 4, c4 = (f & 15) * 4;
            float4 vv = *(const float4*)(v + (baseRow + k0 + kk) * EE + colOff + c4);
            *(float4*)&Tl[kk][c4] = vv;   // row pad 68 keeps 16B alignment
        }
        __syncthreads();
        #pragma unroll 16
        for (int kk = 0; kk < 64; ++kk) {
            float p = S[wq][k0 + kk];
            y0 = fmaf(p, Tl[kk][lane],      y0);
            y1 = fmaf(p, Tl[kk][lane + 32], y1);
        }
        __syncthreads();
    }
    y[(baseRow + q0 + wq) * EE + colOff + lane]      = y0;
    y[(baseRow + q0 + wq) * EE + colOff + lane + 32] = y1;
}

// ---------------------------------------------------------------------------
// Launch
// ---------------------------------------------------------------------------
extern "C" void kernel_launch(void* const* d_in, const int* in_sizes, int n_in,
                              void* d_out, int out_size)
{
    const int*   x     = (const int*)  d_in[0];
    // d_in[1] = targets (unused)
    const float* tok   = (const float*)d_in[2];
    const float* pos   = (const float*)d_in[3];
    const float* ln1g  = (const float*)d_in[4];
    const float* ln1b  = (const float*)d_in[5];
    const float* Wq    = (const float*)d_in[6];
    const float* bq    = (const float*)d_in[7];
    const float* Wk    = (const float*)d_in[8];
    const float* bk    = (const float*)d_in[9];
    const float* Wv    = (const float*)d_in[10];
    const float* bv    = (const float*)d_in[11];
    const float* Wp    = (const float*)d_in[12];
    const float* bp    = (const float*)d_in[13];
    const float* ln2g  = (const float*)d_in[14];
    const float* ln2b  = (const float*)d_in[15];
    const float* Wf1   = (const float*)d_in[16];
    const float* bf1   = (const float*)d_in[17];
    const float* Wf2   = (const float*)d_in[18];
    const float* bf2   = (const float*)d_in[19];
    const float* lnfg  = (const float*)d_in[20];
    const float* lnfb  = (const float*)d_in[21];
    const float* headw = (const float*)d_in[22];
    float* out = (float*)d_out;

    float *h, *xn, *q, *k, *v, *y, *mlp;
    cudaGetSymbolAddress((void**)&h,   g_h);
    cudaGetSymbolAddress((void**)&xn,  g_xn);
    cudaGetSymbolAddress((void**)&q,   g_q);
    cudaGetSymbolAddress((void**)&k,   g_k);
    cudaGetSymbolAddress((void**)&v,   g_v);
    cudaGetSymbolAddress((void**)&y,   g_y);
    cudaGetSymbolAddress((void**)&mlp, g_mlp);

    embed_kernel<<<MR, 256>>>(x, tok, pos, h);

    dim3 gE (EE / GBN, MR / GBM);   // N=1024
    dim3 gF1(FF / GBN, MR / GBM);   // N=4096
    dim3 gHd(VV / GBN, MR / GBM);   // N=512

    for (int l = 0; l < LL; ++l) {
        size_t oE  = (size_t)l * EE;
        size_t oEE = (size_t)l * EE * EE;
        size_t oF  = (size_t)l * FF;
        size_t oEF = (size_t)l * EE * FF;

        ln_kernel<<<MR, 256>>>(h, ln1g + oE, ln1b + oE, xn);

        gemm_kernel<<<gE, 256>>>(xn, Wq + oEE, bq + oE, nullptr, q, MR, EE, EE, 0);
        gemm_kernel<<<gE, 256>>>(xn, Wk + oEE, bk + oE, nullptr, k, MR, EE, EE, 0);
        gemm_kernel<<<gE, 256>>>(xn, Wv + oEE, bv + oE, nullptr, v, MR, EE, EE, 0);

        attn_kernel<<<BB * HH * (TT / AQ), 256>>>(q, k, v, y);

        // h = h + y @ Wp + bp
        gemm_kernel<<<gE, 256>>>(y, Wp + oEE, bp + oE, h, h, MR, EE, EE, 0);

        ln_kernel<<<MR, 256>>>(h, ln2g + oE, ln2b + oE, xn);

        // mlp = gelu(xn @ Wf1 + bf1)
        gemm_kernel<<<gF1, 256>>>(xn, Wf1 + oEF, bf1 + oF, nullptr, mlp, MR, FF, EE, 1);

        // h = h + mlp @ Wf2 + bf2
        gemm_kernel<<<gE, 256>>>(mlp, Wf2 + oEF, bf2 + oE, h, h, MR, EE, FF, 0);
    }

    ln_kernel<<<MR, 256>>>(h, lnfg, lnfb, xn);
    gemm_kernel<<<gHd, 256>>>(xn, headw, nullptr, nullptr, out, MR, VV, EE, 0);
}

// round 10
// speedup vs baseline: 1.7506x; 1.7506x over previous
#include <cuda_runtime.h>
#include <cuda_bf16.h>
#include <math.h>
#include <stdint.h>

// ---------------------------------------------------------------------------
// GPT-2 forward. B=8 T=512 E=1024 H=16 D=64 F=4096 V=512 L=12
// Round 8: GEMMs on mma.sync.m16n8k16 bf16 (HMMA) with 3-term hi/lo split.
//          (tcgen05 is unreachable: harness builds via compute_103, not _103a)
// ---------------------------------------------------------------------------

#define EE   1024
#define TT   512
#define BB   8
#define VV   512
#define LL   12
#define FF   4096
#define MR   4096
#define HH   16
#define DD   64

// ---------------- scratch (device globals; allocation-free rule) -----------
__device__ float g_h [(size_t)MR * EE];
__device__ float g_q [(size_t)MR * EE];
__device__ float g_k [(size_t)MR * EE];
__device__ float g_v [(size_t)MR * EE];

__device__ __nv_bfloat16 g_xn_h[(size_t)MR * EE];
__device__ __nv_bfloat16 g_xn_l[(size_t)MR * EE];
__device__ __nv_bfloat16 g_y_h [(size_t)MR * EE];
__device__ __nv_bfloat16 g_y_l [(size_t)MR * EE];
__device__ __nv_bfloat16 g_mlp_h[(size_t)MR * FF];
__device__ __nv_bfloat16 g_mlp_l[(size_t)MR * FF];

// transposed bf16 weights [N][K] per layer, hi/lo
__device__ __nv_bfloat16 g_wqT_h[(size_t)LL * EE * EE];
__device__ __nv_bfloat16 g_wqT_l[(size_t)LL * EE * EE];
__device__ __nv_bfloat16 g_wkT_h[(size_t)LL * EE * EE];
__device__ __nv_bfloat16 g_wkT_l[(size_t)LL * EE * EE];
__device__ __nv_bfloat16 g_wvT_h[(size_t)LL * EE * EE];
__device__ __nv_bfloat16 g_wvT_l[(size_t)LL * EE * EE];
__device__ __nv_bfloat16 g_wpT_h[(size_t)LL * EE * EE];
__device__ __nv_bfloat16 g_wpT_l[(size_t)LL * EE * EE];
__device__ __nv_bfloat16 g_f1T_h[(size_t)LL * EE * FF];
__device__ __nv_bfloat16 g_f1T_l[(size_t)LL * EE * FF];
__device__ __nv_bfloat16 g_f2T_h[(size_t)LL * EE * FF];
__device__ __nv_bfloat16 g_f2T_l[(size_t)LL * EE * FF];
__device__ __nv_bfloat16 g_hdT_h[(size_t)VV * EE];
__device__ __nv_bfloat16 g_hdT_l[(size_t)VV * EE];

// ---------------------------- PTX helpers ----------------------------------
__device__ __forceinline__ uint32_t smem_u32(const void* p) {
    uint32_t a;
    asm("{ .reg .u64 t; cvta.to.shared.u64 t, %1; cvt.u32.u64 %0, t; }"
        : "=r"(a) : "l"(p));
    return a;
}

__device__ __forceinline__ void cp_async16(uint32_t dst, const void* src) {
    asm volatile("cp.async.cg.shared.global [%0], [%1], 16;"
                 :: "r"(dst), "l"(src));
}
#define CP_COMMIT() asm volatile("cp.async.commit_group;" ::: "memory")
#define CP_WAIT(n)  asm volatile("cp.async.wait_group %0;" :: "n"(n) : "memory")

__device__ __forceinline__ void ldsm4(uint32_t& r0, uint32_t& r1,
                                      uint32_t& r2, uint32_t& r3, uint32_t a) {
    asm volatile("ldmatrix.sync.aligned.m8n8.x4.shared.b16 {%0,%1,%2,%3}, [%4];"
                 : "=r"(r0), "=r"(r1), "=r"(r2), "=r"(r3) : "r"(a));
}

__device__ __forceinline__ void mma16816(float* d,
                                         uint32_t a0, uint32_t a1, uint32_t a2, uint32_t a3,
                                         uint32_t b0, uint32_t b1) {
    asm volatile(
        "mma.sync.aligned.m16n8k16.row.col.f32.bf16.bf16.f32 "
        "{%0,%1,%2,%3}, {%4,%5,%6,%7}, {%8,%9}, {%0,%1,%2,%3};"
        : "+f"(d[0]), "+f"(d[1]), "+f"(d[2]), "+f"(d[3])
        : "r"(a0), "r"(a1), "r"(a2), "r"(a3), "r"(b0), "r"(b1));
}

__device__ __forceinline__ void split_bf16(float v, __nv_bfloat16& hi, __nv_bfloat16& lo) {
    hi = __float2bfloat16(v);
    lo = __float2bfloat16(v - __bfloat162float(hi));
}

// ---------------------------------------------------------------------------
// Embedding
// ---------------------------------------------------------------------------
__global__ void embed_kernel(const int* __restrict__ x,
                             const float* __restrict__ tok,
                             const float* __restrict__ pos,
                             float* __restrict__ h)
{
    int row = blockIdx.x;
    int t   = row & (TT - 1);
    int tk  = x[row];
    const float* te = tok + (size_t)tk * EE;
    const float* pe = pos + (size_t)t  * EE;
    float* hr = h + (size_t)row * EE;
    for (int j = threadIdx.x; j < EE; j += blockDim.x)
        hr[j] = te[j] + pe[j];
}

// ---------------------------------------------------------------------------
// LayerNorm -> bf16 hi/lo outputs
// ---------------------------------------------------------------------------
__global__ void ln_kernel(const float* __restrict__ x,
                          const float* __restrict__ g,
                          const float* __restrict__ b,
                          __nv_bfloat16* __restrict__ oh,
                          __nv_bfloat16* __restrict__ ol)
{
    int row = blockIdx.x;
    const float* xr = x + (size_t)row * EE;
    float s = 0.f, s2 = 0.f;
    for (int j = threadIdx.x; j < EE; j += 256) {
        float v = xr[j];
        s += v; s2 += v * v;
    }
    #pragma unroll
    for (int o = 16; o; o >>= 1) {
        s  += __shfl_xor_sync(0xffffffffu, s,  o);
        s2 += __shfl_xor_sync(0xffffffffu, s2, o);
    }
    __shared__ float sh[2][8];
    int w = threadIdx.x >> 5, lane = threadIdx.x & 31;
    if (lane == 0) { sh[0][w] = s; sh[1][w] = s2; }
    __syncthreads();
    if (w == 0) {
        s  = (lane < 8) ? sh[0][lane] : 0.f;
        s2 = (lane < 8) ? sh[1][lane] : 0.f;
        #pragma unroll
        for (int o = 4; o; o >>= 1) {
            s  += __shfl_xor_sync(0xffffffffu, s,  o);
            s2 += __shfl_xor_sync(0xffffffffu, s2, o);
        }
        if (lane == 0) { sh[0][0] = s; sh[1][0] = s2; }
    }
    __syncthreads();
    s = sh[0][0]; s2 = sh[1][0];
    float mu  = s * (1.f / EE);
    float var = s2 * (1.f / EE) - mu * mu;
    float rs  = rsqrtf(var + 1e-5f);
    size_t ro = (size_t)row * EE;
    for (int j = threadIdx.x; j < EE; j += 256) {
        float vv = (xr[j] - mu) * rs * g[j] + b[j];
        __nv_bfloat16 hi, lo; split_bf16(vv, hi, lo);
        oh[ro + j] = hi; ol[ro + j] = lo;
    }
}

// ---------------------------------------------------------------------------
// Weight convert + transpose: W[K][N] fp32 -> Wt[N][K] bf16 hi/lo. grid.z = layer
// ---------------------------------------------------------------------------
__global__ void wconv_kernel(const float* __restrict__ W,
                             __nv_bfloat16* __restrict__ Th,
                             __nv_bfloat16* __restrict__ Tl,
                             int K, int N)
{
    __shared__ float t[32][33];
    size_t lo = (size_t)blockIdx.z * K * N;
    const float* Wl = W + lo;
    __nv_bfloat16* Thl = Th + lo;
    __nv_bfloat16* Tll = Tl + lo;
    int n0 = blockIdx.x * 32, k0 = blockIdx.y * 32;
    int tx = threadIdx.x, ty = threadIdx.y;
    #pragma unroll
    for (int i = 0; i < 4; i++)
        t[ty + i * 8][tx] = Wl[(size_t)(k0 + ty + i * 8) * N + n0 + tx];
    __syncthreads();
    #pragma unroll
    for (int i = 0; i < 4; i++) {
        int r = ty + i * 8;
        float v = t[tx][r];
        __nv_bfloat16 hi, lw; split_bf16(v, hi, lw);
        size_t o = (size_t)(n0 + r) * K + k0 + tx;
        Thl[o] = hi; Tll[o] = lw;
    }
}

// ---------------------------------------------------------------------------
// HMMA GEMM: out = act(A @ Wt^T + bias) (+res)
//   A: [M][K] bf16 hi/lo, Wt: [N][K] bf16 hi/lo (both K-major)
//   3-term: Ah*Bh + Ah*Bl + Al*Bh, fp32 accum in registers.
//   CTA 128x128, 8 warps (4x2), warp tile 32x64, BK=32, cp.async double-buffer.
//   smem rows padded to 80B -> conflict-free ldmatrix.
// ---------------------------------------------------------------------------
#define BK      32
#define ROWB    80                    // padded row bytes (32 bf16 + 8 pad)
#define TILE_B  (128 * ROWB)          // 10240 B
#define STAGE_B (4 * TILE_B)          // Ah,Al,Bh,Bl = 40960 B
#define GEMM_SMEM (2 * STAGE_B)       // 81920 B

__global__ __launch_bounds__(256)
void mma_gemm(const __nv_bfloat16* __restrict__ Ah, const __nv_bfloat16* __restrict__ Al,
              const __nv_bfloat16* __restrict__ Bh, const __nv_bfloat16* __restrict__ Bl,
              const float* __restrict__ bias, const float* __restrict__ res,
              float* __restrict__ outF,
              __nv_bfloat16* __restrict__ outH, __nv_bfloat16* __restrict__ outL,
              int M, int N, int K, int act)
{
    extern __shared__ char dsm[];
    uint32_t sbase = smem_u32(dsm);

    int tid  = threadIdx.x;
    int wid  = tid >> 5, lane = tid & 31;
    int wm   = wid >> 1;              // 0..3
    int wn   = wid & 1;               // 0..1
    int row0 = blockIdx.y * 128;
    int col0 = blockIdx.x * 128;

    const __nv_bfloat16* srcs[4] = {Ah, Al, Bh, Bl};
    int rbs[4] = {row0, row0, col0, col0};

    float acc[2][8][4];
    #pragma unroll
    for (int i = 0; i < 2; i++)
        #pragma unroll
        for (int j = 0; j < 8; j++)
            #pragma unroll
            for (int c = 0; c < 4; c++) acc[i][j][c] = 0.f;

    int nch = K / BK;

    // ---- prologue: stage 0 loads ----
    #pragma unroll
    for (int t4 = 0; t4 < 4; ++t4) {
        const __nv_bfloat16* src = srcs[t4];
        int rb = rbs[t4];
        #pragma unroll
        for (int rep = 0; rep < 2; ++rep) {
            int idx = tid + rep * 256;          // 0..511
            int r = idx >> 2, u = idx & 3;
            cp_async16(sbase + t4 * TILE_B + r * ROWB + u * 16,
                       src + (size_t)(rb + r) * K + u * 8);
        }
    }
    CP_COMMIT();

    int buf = 0;
    for (int ch = 0; ch < nch; ++ch) {
        if (ch + 1 < nch) {
            int kb = (ch + 1) * BK;
            uint32_t st = sbase + (buf ^ 1) * STAGE_B;
            #pragma unroll
            for (int t4 = 0; t4 < 4; ++t4) {
                const __nv_bfloat16* src = srcs[t4];
                int rb = rbs[t4];
                #pragma unroll
                for (int rep = 0; rep < 2; ++rep) {
                    int idx = tid + rep * 256;
                    int r = idx >> 2, u = idx & 3;
                    cp_async16(st + t4 * TILE_B + r * ROWB + u * 16,
                               src + (size_t)(rb + r) * K + kb + u * 8);
                }
            }
            CP_COMMIT();
            CP_WAIT(1);
        } else {
            CP_WAIT(0);
        }
        __syncthreads();

        uint32_t st  = sbase + buf * STAGE_B;
        uint32_t sAh = st;
        uint32_t sAl = st + TILE_B;
        uint32_t sBh = st + 2 * TILE_B;
        uint32_t sBl = st + 3 * TILE_B;

        #pragma unroll
        for (int ks = 0; ks < 2; ++ks) {
            // A fragments: rows wm*32 + im*16 + (lane&15), k half = (lane>>4)*8
            uint32_t ah[2][4], al[2][4];
            int ar  = (lane & 15);
            int akb = ks * 16 + ((lane >> 4) << 3);
            #pragma unroll
            for (int im = 0; im < 2; ++im) {
                uint32_t off = (uint32_t)(wm * 32 + im * 16 + ar) * ROWB + akb * 2;
                ldsm4(ah[im][0], ah[im][1], ah[im][2], ah[im][3], sAh + off);
                ldsm4(al[im][0], al[im][1], al[im][2], al[im][3], sAl + off);
            }
            // B fragments in blocks of 4 n8-groups (2 ldmatrix.x4 per term)
            #pragma unroll
            for (int jb = 0; jb < 8; jb += 4) {
                uint32_t bh[4][2], bl[4][2];
                #pragma unroll
                for (int p = 0; p < 2; ++p) {         // pair p covers j = jb+2p, jb+2p+1
                    int j0 = jb + 2 * p;
                    int n  = wn * 64 + (j0 + ((lane >> 4) & 1)) * 8 + (lane & 7);
                    int kc = ks * 16 + (((lane >> 3) & 1) << 3);
                    uint32_t off = (uint32_t)n * ROWB + kc * 2;
                    ldsm4(bh[2*p][0], bh[2*p][1], bh[2*p+1][0], bh[2*p+1][1], sBh + off);
                    ldsm4(bl[2*p][0], bl[2*p][1], bl[2*p+1][0], bl[2*p+1][1], sBl + off);
                }
                #pragma unroll
                for (int im = 0; im < 2; ++im)
                    #pragma unroll
                    for (int jj = 0; jj < 4; ++jj) {
                        float* d = acc[im][jb + jj];
                        mma16816(d, ah[im][0], ah[im][1], ah[im][2], ah[im][3],
                                 bh[jj][0], bh[jj][1]);
                        mma16816(d, ah[im][0], ah[im][1], ah[im][2], ah[im][3],
                                 bl[jj][0], bl[jj][1]);
                        mma16816(d, al[im][0], al[im][1], al[im][2], al[im][3],
                                 bh[jj][0], bh[jj][1]);
                    }
            }
        }
        __syncthreads();
        buf ^= 1;
    }

    // ---- epilogue ----
    int gid = lane >> 2, tig = lane & 3;
    #pragma unroll
    for (int im = 0; im < 2; ++im) {
        #pragma unroll
        for (int j = 0; j < 8; ++j) {
            int col = col0 + wn * 64 + j * 8 + tig * 2;
            #pragma unroll
            for (int hr = 0; hr < 2; ++hr) {
                int row = row0 + wm * 32 + im * 16 + gid + hr * 8;
                float v0 = acc[im][j][hr * 2 + 0];
                float v1 = acc[im][j][hr * 2 + 1];
                size_t off = (size_t)row * N + col;
                if (bias) { v0 += bias[col]; v1 += bias[col + 1]; }
                if (act == 1) {
                    v0 = 0.5f * v0 * (1.f + erff(v0 * 0.70710678118654752f));
                    v1 = 0.5f * v1 * (1.f + erff(v1 * 0.70710678118654752f));
                }
                if (res) { v0 += res[off]; v1 += res[off + 1]; }
                if (outF) {
                    float2 ov; ov.x = v0; ov.y = v1;
                    *(float2*)(outF + off) = ov;
                }
                if (outH) {
                    __nv_bfloat16 h0, l0, h1, l1;
                    split_bf16(v0, h0, l0);
                    split_bf16(v1, h1, l1);
                    __nv_bfloat162 hv; hv.x = h0; hv.y = h1;
                    __nv_bfloat162 lv; lv.x = l0; lv.y = l1;
                    *(__nv_bfloat162*)(outH + off) = hv;
                    *(__nv_bfloat162*)(outL + off) = lv;
                }
            }
        }
    }
}

// ---------------------------------------------------------------------------
// Attention (fp32) -> y as bf16 hi/lo
// ---------------------------------------------------------------------------
#define AQ 8

__global__ __launch_bounds__(256)
void attn_kernel(const float* __restrict__ q, const float* __restrict__ k,
                 const float* __restrict__ v,
                 __nv_bfloat16* __restrict__ yh, __nv_bfloat16* __restrict__ yl)
{
    int qt = blockIdx.x & 63;
    int bh = blockIdx.x >> 6;
    int h_ = bh & (HH - 1);
    int b  = bh >> 4;
    int q0 = qt * AQ;
    size_t baseRow = (size_t)b * TT;
    int colOff = h_ * DD;

    __shared__ float Qs[AQ][DD];
    __shared__ float S [AQ][TT];
    __shared__ float Tl[DD][68];

    int tid  = threadIdx.x;
    int lane = tid & 31;
    int wq   = tid >> 5;
    const float scale = 0.125f;

    for (int idx = tid; idx < AQ * DD; idx += 256) {
        int qi = idx >> 6, d = idx & 63;
        Qs[qi][d] = q[(baseRow + q0 + qi) * EE + colOff + d] * scale;
    }

    int qmaxg  = q0 + AQ - 1;
    int ntiles = (qmaxg >> 6) + 1;

    for (int kt = 0; kt < ntiles; ++kt) {
        int k0 = kt * 64;
        __syncthreads();
        for (int f = tid; f < 64 * 16; f += 256) {
            int kk = f >> 4, c4 = (f & 15) * 4;
            float4 kv = *(const float4*)(k + (baseRow + k0 + kk) * EE + colOff + c4);
            Tl[c4 + 0][kk] = kv.x;
            Tl[c4 + 1][kk] = kv.y;
            Tl[c4 + 2][kk] = kv.z;
            Tl[c4 + 3][kk] = kv.w;
        }
        __syncthreads();
        float s0 = 0.f, s1 = 0.f;
        #pragma unroll 16
        for (int d = 0; d < DD; ++d) {
            float qv = Qs[wq][d];
            s0 = fmaf(qv, Tl[d][lane],      s0);
            s1 = fmaf(qv, Tl[d][lane + 32], s1);
        }
        int qg = q0 + wq;
        S[wq][k0 + lane]      = (k0 + lane      <= qg) ? s0 : -INFINITY;
        S[wq][k0 + lane + 32] = (k0 + lane + 32 <= qg) ? s1 : -INFINITY;
    }
    __syncthreads();

    {
        int kmaxb = ntiles * 64;
        float m = -INFINITY;
        for (int kk = lane; kk < kmaxb; kk += 32) m = fmaxf(m, S[wq][kk]);
        #pragma unroll
        for (int o = 16; o; o >>= 1) m = fmaxf(m, __shfl_xor_sync(0xffffffffu, m, o));
        float sum = 0.f;
        for (int kk = lane; kk < kmaxb; kk += 32) {
            float e = __expf(S[wq][kk] - m);
            S[wq][kk] = e;
            sum += e;
        }
        #pragma unroll
        for (int o = 16; o; o >>= 1) sum += __shfl_xor_sync(0xffffffffu, sum, o);
        float inv = 1.f / sum;
        for (int kk = lane; kk < kmaxb; kk += 32) S[wq][kk] *= inv;
    }
    __syncthreads();

    float y0 = 0.f, y1 = 0.f;
    for (int kt = 0; kt < ntiles; ++kt) {
        int k0 = kt * 64;
        for (int f = tid; f < 64 * 16; f += 256) {
            int kk = f >> 4, c4 = (f & 15) * 4;
            float4 vv = *(const float4*)(v + (baseRow + k0 + kk) * EE + colOff + c4);
            *(float4*)&Tl[kk][c4] = vv;
        }
        __syncthreads();
        #pragma unroll 16
        for (int kk = 0; kk < 64; ++kk) {
            float p = S[wq][k0 + kk];
            y0 = fmaf(p, Tl[kk][lane],      y0);
            y1 = fmaf(p, Tl[kk][lane + 32], y1);
        }
        __syncthreads();
    }
    size_t o0 = (baseRow + q0 + wq) * EE + colOff + lane;
    __nv_bfloat16 h0, l0, h1, l1;
    split_bf16(y0, h0, l0);
    split_bf16(y1, h1, l1);
    yh[o0]      = h0; yl[o0]      = l0;
    yh[o0 + 32] = h1; yl[o0 + 32] = l1;
}

// ---------------------------------------------------------------------------
// Launch
// ---------------------------------------------------------------------------
extern "C" void kernel_launch(void* const* d_in, const int* in_sizes, int n_in,
                              void* d_out, int out_size)
{
    const int*   x     = (const int*)  d_in[0];
    const float* tok   = (const float*)d_in[2];
    const float* pos   = (const float*)d_in[3];
    const float* ln1g  = (const float*)d_in[4];
    const float* ln1b  = (const float*)d_in[5];
    const float* Wq    = (const float*)d_in[6];
    const float* bq    = (const float*)d_in[7];
    const float* Wk    = (const float*)d_in[8];
    const float* bk    = (const float*)d_in[9];
    const float* Wv    = (const float*)d_in[10];
    const float* bv    = (const float*)d_in[11];
    const float* Wp    = (const float*)d_in[12];
    const float* bp    = (const float*)d_in[13];
    const float* ln2g  = (const float*)d_in[14];
    const float* ln2b  = (const float*)d_in[15];
    const float* Wf1   = (const float*)d_in[16];
    const float* bf1   = (const float*)d_in[17];
    const float* Wf2   = (const float*)d_in[18];
    const float* bf2   = (const float*)d_in[19];
    const float* lnfg  = (const float*)d_in[20];
    const float* lnfb  = (const float*)d_in[21];
    const float* headw = (const float*)d_in[22];
    float* out = (float*)d_out;

    float *h, *q, *k, *v;
    cudaGetSymbolAddress((void**)&h, g_h);
    cudaGetSymbolAddress((void**)&q, g_q);
    cudaGetSymbolAddress((void**)&k, g_k);
    cudaGetSymbolAddress((void**)&v, g_v);
    __nv_bfloat16 *xnh, *xnl, *yh, *yl, *mh, *ml;
    cudaGetSymbolAddress((void**)&xnh, g_xn_h);
    cudaGetSymbolAddress((void**)&xnl, g_xn_l);
    cudaGetSymbolAddress((void**)&yh,  g_y_h);
    cudaGetSymbolAddress((void**)&yl,  g_y_l);
    cudaGetSymbolAddress((void**)&mh,  g_mlp_h);
    cudaGetSymbolAddress((void**)&ml,  g_mlp_l);
    __nv_bfloat16 *wqh, *wql, *wkh, *wkl, *wvh, *wvl, *wph, *wpl;
    __nv_bfloat16 *f1h, *f1l, *f2h, *f2l, *hdh, *hdl;
    cudaGetSymbolAddress((void**)&wqh, g_wqT_h); cudaGetSymbolAddress((void**)&wql, g_wqT_l);
    cudaGetSymbolAddress((void**)&wkh, g_wkT_h); cudaGetSymbolAddress((void**)&wkl, g_wkT_l);
    cudaGetSymbolAddress((void**)&wvh, g_wvT_h); cudaGetSymbolAddress((void**)&wvl, g_wvT_l);
    cudaGetSymbolAddress((void**)&wph, g_wpT_h); cudaGetSymbolAddress((void**)&wpl, g_wpT_l);
    cudaGetSymbolAddress((void**)&f1h, g_f1T_h); cudaGetSymbolAddress((void**)&f1l, g_f1T_l);
    cudaGetSymbolAddress((void**)&f2h, g_f2T_h); cudaGetSymbolAddress((void**)&f2l, g_f2T_l);
    cudaGetSymbolAddress((void**)&hdh, g_hdT_h); cudaGetSymbolAddress((void**)&hdl, g_hdT_l);

    cudaFuncSetAttribute(mma_gemm, cudaFuncAttributeMaxDynamicSharedMemorySize, GEMM_SMEM);

    // --- weight convert + transpose ---
    dim3 wb(32, 8);
    wconv_kernel<<<dim3(EE / 32, EE / 32, LL), wb>>>(Wq,  wqh, wql, EE, EE);
    wconv_kernel<<<dim3(EE / 32, EE / 32, LL), wb>>>(Wk,  wkh, wkl, EE, EE);
    wconv_kernel<<<dim3(EE / 32, EE / 32, LL), wb>>>(Wv,  wvh, wvl, EE, EE);
    wconv_kernel<<<dim3(EE / 32, EE / 32, LL), wb>>>(Wp,  wph, wpl, EE, EE);
    wconv_kernel<<<dim3(FF / 32, EE / 32, LL), wb>>>(Wf1, f1h, f1l, EE, FF);
    wconv_kernel<<<dim3(EE / 32, FF / 32, LL), wb>>>(Wf2, f2h, f2l, FF, EE);
    wconv_kernel<<<dim3(VV / 32, EE / 32, 1 ), wb>>>(headw, hdh, hdl, EE, VV);

    embed_kernel<<<MR, 256>>>(x, tok, pos, h);

    dim3 gE (EE / 128, MR / 128);
    dim3 gF (FF / 128, MR / 128);
    dim3 gHd(VV / 128, MR / 128);

    for (int l = 0; l < LL; ++l) {
        size_t oE  = (size_t)l * EE;
        size_t oEE = (size_t)l * EE * EE;
        size_t oF  = (size_t)l * FF;
        size_t oEF = (size_t)l * EE * FF;

        ln_kernel<<<MR, 256>>>(h, ln1g + oE, ln1b + oE, xnh, xnl);

        mma_gemm<<<gE, 256, GEMM_SMEM>>>(xnh, xnl, wqh + oEE, wql + oEE,
                                         bq + oE, nullptr, q, nullptr, nullptr,
                                         MR, EE, EE, 0);
        mma_gemm<<<gE, 256, GEMM_SMEM>>>(xnh, xnl, wkh + oEE, wkl + oEE,
                                         bk + oE, nullptr, k, nullptr, nullptr,
                                         MR, EE, EE, 0);
        mma_gemm<<<gE, 256, GEMM_SMEM>>>(xnh, xnl, wvh + oEE, wvl + oEE,
                                         bv + oE, nullptr, v, nullptr, nullptr,
                                         MR, EE, EE, 0);

        attn_kernel<<<BB * HH * (TT / AQ), 256>>>(q, k, v, yh, yl);

        // h = h + y @ Wp + bp
        mma_gemm<<<gE, 256, GEMM_SMEM>>>(yh, yl, wph + oEE, wpl + oEE,
                                         bp + oE, h, h, nullptr, nullptr,
                                         MR, EE, EE, 0);

        ln_kernel<<<MR, 256>>>(h, ln2g + oE, ln2b + oE, xnh, xnl);

        // mlp = gelu(xn @ Wf1 + bf1)  -> bf16 hi/lo
        mma_gemm<<<gF, 256, GEMM_SMEM>>>(xnh, xnl, f1h + oEF, f1l + oEF,
                                         bf1 + oF, nullptr, nullptr, mh, ml,
                                         MR, FF, EE, 1);

        // h = h + mlp @ Wf2 + bf2
        mma_gemm<<<gE, 256, GEMM_SMEM>>>(mh, ml, f2h + oEF, f2l + oEF,
                                         bf2 + oE, h, h, nullptr, nullptr,
                                         MR, EE, FF, 0);
    }

    ln_kernel<<<MR, 256>>>(h, lnfg, lnfb, xnh, xnl);
    mma_gemm<<<gHd, 256, GEMM_SMEM>>>(xnh, xnl, hdh, hdl,
                                      nullptr, nullptr, out, nullptr, nullptr,
                                      MR, VV, EE, 0);
}

// round 13
// speedup vs baseline: 1.7838x; 1.0190x over previous
#include <cuda_runtime.h>
#include <cuda_bf16.h>
#include <math.h>
#include <stdint.h>

// ---------------------------------------------------------------------------
// GPT-2 forward. B=8 T=512 E=1024 H=16 D=64 F=4096 V=512 L=12
// Round 11: HMMA 3-term split GEMM, CTA 128x256 / warp 64x64, fused QKV.
// ---------------------------------------------------------------------------

#define EE   1024
#define TT   512
#define BB   8
#define VV   512
#define LL   12
#define FF   4096
#define MR   4096
#define HH   16
#define DD   64
#define QKVW 3072

// ---------------- scratch (device globals; allocation-free rule) -----------
__device__ float g_h  [(size_t)MR * EE];
__device__ float g_qkv[(size_t)MR * QKVW];

__device__ __nv_bfloat16 g_xn_h[(size_t)MR * EE];
__device__ __nv_bfloat16 g_xn_l[(size_t)MR * EE];
__device__ __nv_bfloat16 g_y_h [(size_t)MR * EE];
__device__ __nv_bfloat16 g_y_l [(size_t)MR * EE];
__device__ __nv_bfloat16 g_mlp_h[(size_t)MR * FF];
__device__ __nv_bfloat16 g_mlp_l[(size_t)MR * FF];

// transposed bf16 weights [N][K] per layer, hi/lo
__device__ __nv_bfloat16 g_wqkvT_h[(size_t)LL * QKVW * EE];
__device__ __nv_bfloat16 g_wqkvT_l[(size_t)LL * QKVW * EE];
__device__ float         g_bqkv  [(size_t)LL * QKVW];
__device__ __nv_bfloat16 g_wpT_h[(size_t)LL * EE * EE];
__device__ __nv_bfloat16 g_wpT_l[(size_t)LL * EE * EE];
__device__ __nv_bfloat16 g_f1T_h[(size_t)LL * EE * FF];
__device__ __nv_bfloat16 g_f1T_l[(size_t)LL * EE * FF];
__device__ __nv_bfloat16 g_f2T_h[(size_t)LL * EE * FF];
__device__ __nv_bfloat16 g_f2T_l[(size_t)LL * EE * FF];
__device__ __nv_bfloat16 g_hdT_h[(size_t)VV * EE];
__device__ __nv_bfloat16 g_hdT_l[(size_t)VV * EE];

// ---------------------------- PTX helpers ----------------------------------
__device__ __forceinline__ uint32_t smem_u32(const void* p) {
    uint32_t a;
    asm("{ .reg .u64 t; cvta.to.shared.u64 t, %1; cvt.u32.u64 %0, t; }"
        : "=r"(a) : "l"(p));
    return a;
}

__device__ __forceinline__ void cp_async16(uint32_t dst, const void* src) {
    asm volatile("cp.async.cg.shared.global [%0], [%1], 16;"
                 :: "r"(dst), "l"(src));
}
#define CP_COMMIT() asm volatile("cp.async.commit_group;" ::: "memory")
#define CP_WAIT(n)  asm volatile("cp.async.wait_group %0;" :: "n"(n) : "memory")

__device__ __forceinline__ void ldsm4(uint32_t& r0, uint32_t& r1,
                                      uint32_t& r2, uint32_t& r3, uint32_t a) {
    asm volatile("ldmatrix.sync.aligned.m8n8.x4.shared.b16 {%0,%1,%2,%3}, [%4];"
                 : "=r"(r0), "=r"(r1), "=r"(r2), "=r"(r3) : "r"(a));
}

__device__ __forceinline__ void mma16816(float* d,
                                         uint32_t a0, uint32_t a1, uint32_t a2, uint32_t a3,
                                         uint32_t b0, uint32_t b1) {
    asm volatile(
        "mma.sync.aligned.m16n8k16.row.col.f32.bf16.bf16.f32 "
        "{%0,%1,%2,%3}, {%4,%5,%6,%7}, {%8,%9}, {%0,%1,%2,%3};"
        : "+f"(d[0]), "+f"(d[1]), "+f"(d[2]), "+f"(d[3])
        : "r"(a0), "r"(a1), "r"(a2), "r"(a3), "r"(b0), "r"(b1));
}

__device__ __forceinline__ void split_bf16(float v, __nv_bfloat16& hi, __nv_bfloat16& lo) {
    hi = __float2bfloat16(v);
    lo = __float2bfloat16(v - __bfloat162float(hi));
}

// ---------------------------------------------------------------------------
// Embedding
// ---------------------------------------------------------------------------
__global__ void embed_kernel(const int* __restrict__ x,
                             const float* __restrict__ tok,
                             const float* __restrict__ pos,
                             float* __restrict__ h)
{
    int row = blockIdx.x;
    int t   = row & (TT - 1);
    int tk  = x[row];
    const float* te = tok + (size_t)tk * EE;
    const float* pe = pos + (size_t)t  * EE;
    float* hr = h + (size_t)row * EE;
    for (int j = threadIdx.x; j < EE; j += blockDim.x)
        hr[j] = te[j] + pe[j];
}

// ---------------------------------------------------------------------------
// LayerNorm -> bf16 hi/lo outputs
// ---------------------------------------------------------------------------
__global__ void ln_kernel(const float* __restrict__ x,
                          const float* __restrict__ g,
                          const float* __restrict__ b,
                          __nv_bfloat16* __restrict__ oh,
                          __nv_bfloat16* __restrict__ ol)
{
    int row = blockIdx.x;
    const float* xr = x + (size_t)row * EE;
    float s = 0.f, s2 = 0.f;
    for (int j = threadIdx.x; j < EE; j += 256) {
        float v = xr[j];
        s += v; s2 += v * v;
    }
    #pragma unroll
    for (int o = 16; o; o >>= 1) {
        s  += __shfl_xor_sync(0xffffffffu, s,  o);
        s2 += __shfl_xor_sync(0xffffffffu, s2, o);
    }
    __shared__ float sh[2][8];
    int w = threadIdx.x >> 5, lane = threadIdx.x & 31;
    if (lane == 0) { sh[0][w] = s; sh[1][w] = s2; }
    __syncthreads();
    if (w == 0) {
        s  = (lane < 8) ? sh[0][lane] : 0.f;
        s2 = (lane < 8) ? sh[1][lane] : 0.f;
        #pragma unroll
        for (int o = 4; o; o >>= 1) {
            s  += __shfl_xor_sync(0xffffffffu, s,  o);
            s2 += __shfl_xor_sync(0xffffffffu, s2, o);
        }
        if (lane == 0) { sh[0][0] = s; sh[1][0] = s2; }
    }
    __syncthreads();
    s = sh[0][0]; s2 = sh[1][0];
    float mu  = s * (1.f / EE);
    float var = s2 * (1.f / EE) - mu * mu;
    float rs  = rsqrtf(var + 1e-5f);
    size_t ro = (size_t)row * EE;
    for (int j = threadIdx.x; j < EE; j += 256) {
        float vv = (xr[j] - mu) * rs * g[j] + b[j];
        __nv_bfloat16 hi, lo; split_bf16(vv, hi, lo);
        oh[ro + j] = hi; ol[ro + j] = lo;
    }
}

// ---------------------------------------------------------------------------
// Weight convert + transpose: W[K][N] fp32 -> Wt[N][K] bf16 hi/lo.
// grid.z = layer; outLS = per-layer element stride of output buffer.
// ---------------------------------------------------------------------------
__global__ void wconv_kernel(const float* __restrict__ W,
                             __nv_bfloat16* __restrict__ Th,
                             __nv_bfloat16* __restrict__ Tl,
                             int K, int N, size_t outLS)
{
    __shared__ float t[32][33];
    const float* Wl = W + (size_t)blockIdx.z * K * N;
    __nv_bfloat16* Thl = Th + (size_t)blockIdx.z * outLS;
    __nv_bfloat16* Tll = Tl + (size_t)blockIdx.z * outLS;
    int n0 = blockIdx.x * 32, k0 = blockIdx.y * 32;
    int tx = threadIdx.x, ty = threadIdx.y;
    #pragma unroll
    for (int i = 0; i < 4; i++)
        t[ty + i * 8][tx] = Wl[(size_t)(k0 + ty + i * 8) * N + n0 + tx];
    __syncthreads();
    #pragma unroll
    for (int i = 0; i < 4; i++) {
        int r = ty + i * 8;
        float v = t[tx][r];
        __nv_bfloat16 hi, lw; split_bf16(v, hi, lw);
        size_t o = (size_t)(n0 + r) * K + k0 + tx;
        Thl[o] = hi; Tll[o] = lw;
    }
}

// pack QKV biases: out[l][sec*1024 + j] = b_sec[l][j]
__global__ void packb_kernel(const float* __restrict__ bq,
                             const float* __restrict__ bk,
                             const float* __restrict__ bv,
                             float* __restrict__ out)
{
    int l = blockIdx.x / 3, sec = blockIdx.x % 3;
    const float* src = (sec == 0) ? bq : (sec == 1) ? bk : bv;
    out[(size_t)l * QKVW + sec * EE + threadIdx.x] = src[(size_t)l * EE + threadIdx.x];
}

// ---------------------------------------------------------------------------
// HMMA GEMM: out = act(A @ Wt^T + bias) (+res)
//   A: [M][K] bf16 hi/lo, Wt: [N][K] bf16 hi/lo (both K-major)
//   3-term: Ah*Bh + Ah*Bl + Al*Bh, fp32 accum in registers.
//   CTA 128x256, 8 warps (2x4), warp tile 64x64, BK=32, cp.async double-buffer.
//   smem rows padded to 80B -> conflict-free ldmatrix.
// ---------------------------------------------------------------------------
#define BK      32
#define ROWB    80
#define A_TILE  (128 * ROWB)          // 10240 B
#define B_TILE  (256 * ROWB)          // 20480 B
#define OFF_AH  0
#define OFF_AL  A_TILE
#define OFF_BH  (2 * A_TILE)
#define OFF_BL  (2 * A_TILE + B_TILE)
#define STAGE_B (2 * A_TILE + 2 * B_TILE)   // 61440 B
#define GEMM_SMEM (2 * STAGE_B)             // 122880 B

__global__ __launch_bounds__(256)
void mma_gemm(const __nv_bfloat16* __restrict__ Ah, const __nv_bfloat16* __restrict__ Al,
              const __nv_bfloat16* __restrict__ Bh, const __nv_bfloat16* __restrict__ Bl,
              const float* __restrict__ bias, const float* __restrict__ res,
              float* __restrict__ outF,
              __nv_bfloat16* __restrict__ outH, __nv_bfloat16* __restrict__ outL,
              int M, int N, int K, int act)
{
    extern __shared__ char dsm[];
    uint32_t sbase = smem_u32(dsm);

    int tid  = threadIdx.x;
    int wid  = tid >> 5, lane = tid & 31;
    int wm   = wid >> 2;              // 0..1  (64-row slab)
    int wn   = wid & 3;               // 0..3  (64-col slab)
    int row0 = blockIdx.y * 128;
    int col0 = blockIdx.x * 256;

    float acc[4][8][4];
    #pragma unroll
    for (int i = 0; i < 4; i++)
        #pragma unroll
        for (int j = 0; j < 8; j++)
            #pragma unroll
            for (int c = 0; c < 4; c++) acc[i][j][c] = 0.f;

    int nch = K / BK;

    // ---- stage loader: A (128 rows) hi/lo, B (256 rows) hi/lo ----
    // A: 512 16B-chunks per tile -> 2/thread.  B: 1024 -> 4/thread.
    #define LOAD_STAGE(stU, kb)                                                   \
    do {                                                                          \
        _Pragma("unroll")                                                         \
        for (int rep = 0; rep < 2; ++rep) {                                       \
            int idx = tid + rep * 256;                                            \
            int r = idx >> 2, u = idx & 3;                                        \
            cp_async16((stU) + OFF_AH + r * ROWB + u * 16,                        \
                       Ah + (size_t)(row0 + r) * K + (kb) + u * 8);               \
            cp_async16((stU) + OFF_AL + r * ROWB + u * 16,                        \
                       Al + (size_t)(row0 + r) * K + (kb) + u * 8);               \
        }                                                                         \
        _Pragma("unroll")                                                         \
        for (int rep = 0; rep < 4; ++rep) {                                       \
            int idx = tid + rep * 256;                                            \
            int r = idx >> 2, u = idx & 3;                                        \
            cp_async16((stU) + OFF_BH + r * ROWB + u * 16,                        \
                       Bh + (size_t)(col0 + r) * K + (kb) + u * 8);               \
            cp_async16((stU) + OFF_BL + r * ROWB + u * 16,                        \
                       Bl + (size_t)(col0 + r) * K + (kb) + u * 8);               \
        }                                                                         \
    } while (0)

    LOAD_STAGE(sbase, 0);
    CP_COMMIT();

    int buf = 0;
    for (int ch = 0; ch < nch; ++ch) {
        if (ch + 1 < nch) {
            uint32_t st = sbase + (buf ^ 1) * STAGE_B;
            LOAD_STAGE(st, (ch + 1) * BK);
            CP_COMMIT();
            CP_WAIT(1);
        } else {
            CP_WAIT(0);
        }
        __syncthreads();

        uint32_t st  = sbase + buf * STAGE_B;
        uint32_t sAh = st + OFF_AH;
        uint32_t sAl = st + OFF_AL;
        uint32_t sBh = st + OFF_BH;
        uint32_t sBl = st + OFF_BL;

        #pragma unroll
        for (int ks = 0; ks < 2; ++ks) {
            uint32_t ah[4][4], al[4][4];
            int ar  = (lane & 15);
            int akb = ks * 16 + ((lane >> 4) << 3);
            #pragma unroll
            for (int im = 0; im < 4; ++im) {
                uint32_t off = (uint32_t)(wm * 64 + im * 16 + ar) * ROWB + akb * 2;
                ldsm4(ah[im][0], ah[im][1], ah[im][2], ah[im][3], sAh + off);
                ldsm4(al[im][0], al[im][1], al[im][2], al[im][3], sAl + off);
            }
            #pragma unroll
            for (int jb = 0; jb < 8; jb += 4) {
                uint32_t bh[4][2], bl[4][2];
                #pragma unroll
                for (int p = 0; p < 2; ++p) {
                    int j0 = jb + 2 * p;
                    int n  = wn * 64 + (j0 + ((lane >> 4) & 1)) * 8 + (lane & 7);
                    int kc = ks * 16 + (((lane >> 3) & 1) << 3);
                    uint32_t off = (uint32_t)n * ROWB + kc * 2;
                    ldsm4(bh[2*p][0], bh[2*p][1], bh[2*p+1][0], bh[2*p+1][1], sBh + off);
                    ldsm4(bl[2*p][0], bl[2*p][1], bl[2*p+1][0], bl[2*p+1][1], sBl + off);
                }
                #pragma unroll
                for (int im = 0; im < 4; ++im)
                    #pragma unroll
                    for (int jj = 0; jj < 4; ++jj) {
                        float* d = acc[im][jb + jj];
                        mma16816(d, ah[im][0], ah[im][1], ah[im][2], ah[im][3],
                                 bh[jj][0], bh[jj][1]);
                        mma16816(d, ah[im][0], ah[im][1], ah[im][2], ah[im][3],
                                 bl[jj][0], bl[jj][1]);
                        mma16816(d, al[im][0], al[im][1], al[im][2], al[im][3],
                                 bh[jj][0], bh[jj][1]);
                    }
            }
        }
        __syncthreads();
        buf ^= 1;
    }

    // ---- epilogue ----
    int gid = lane >> 2, tig = lane & 3;
    #pragma unroll
    for (int im = 0; im < 4; ++im) {
        #pragma unroll
        for (int j = 0; j < 8; ++j) {
            int col = col0 + wn * 64 + j * 8 + tig * 2;
            #pragma unroll
            for (int hr = 0; hr < 2; ++hr) {
                int row = row0 + wm * 64 + im * 16 + gid + hr * 8;
                float v0 = acc[im][j][hr * 2 + 0];
                float v1 = acc[im][j][hr * 2 + 1];
                size_t off = (size_t)row * N + col;
                if (bias) { v0 += bias[col]; v1 += bias[col + 1]; }
                if (act == 1) {
                    v0 = 0.5f * v0 * (1.f + erff(v0 * 0.70710678118654752f));
                    v1 = 0.5f * v1 * (1.f + erff(v1 * 0.70710678118654752f));
                }
                if (res) { v0 += res[off]; v1 += res[off + 1]; }
                if (outF) {
                    float2 ov; ov.x = v0; ov.y = v1;
                    *(float2*)(outF + off) = ov;
                }
                if (outH) {
                    __nv_bfloat16 h0, l0, h1, l1;
                    split_bf16(v0, h0, l0);
                    split_bf16(v1, h1, l1);
                    __nv_bfloat162 hv; hv.x = h0; hv.y = h1;
                    __nv_bfloat162 lv; lv.x = l0; lv.y = l1;
                    *(__nv_bfloat162*)(outH + off) = hv;
                    *(__nv_bfloat162*)(outL + off) = lv;
                }
            }
        }
    }
}

// ---------------------------------------------------------------------------
// Attention over fused qkv buffer -> y as bf16 hi/lo
// ---------------------------------------------------------------------------
#define AQ 8

__global__ __launch_bounds__(256)
void attn_kernel(const float* __restrict__ qkv,
                 __nv_bfloat16* __restrict__ yh, __nv_bfloat16* __restrict__ yl)
{
    int qt = blockIdx.x & 63;
    int bh = blockIdx.x >> 6;
    int h_ = bh & (HH - 1);
    int b  = bh >> 4;
    int q0 = qt * AQ;
    size_t baseRow = (size_t)b * TT;
    int colOff = h_ * DD;

    const float* q = qkv + colOff;
    const float* k = qkv + EE + colOff;
    const float* v = qkv + 2 * EE + colOff;

    __shared__ float Qs[AQ][DD];
    __shared__ float S [AQ][TT];
    __shared__ float Tl[DD][68];

    int tid  = threadIdx.x;
    int lane = tid & 31;
    int wq   = tid >> 5;
    const float scale = 0.125f;

    for (int idx = tid; idx < AQ * DD; idx += 256) {
        int qi = idx >> 6, d = idx & 63;
        Qs[qi][d] = q[(baseRow + q0 + qi) * QKVW + d] * scale;
    }

    int qmaxg  = q0 + AQ - 1;
    int ntiles = (qmaxg >> 6) + 1;

    for (int kt = 0; kt < ntiles; ++kt) {
        int k0 = kt * 64;
        __syncthreads();
        for (int f = tid; f < 64 * 16; f += 256) {
            int kk = f >> 4, c4 = (f & 15) * 4;
            float4 kv = *(const float4*)(k + (baseRow + k0 + kk) * QKVW + c4);
            Tl[c4 + 0][kk] = kv.x;
            Tl[c4 + 1][kk] = kv.y;
            Tl[c4 + 2][kk] = kv.z;
            Tl[c4 + 3][kk] = kv.w;
        }
        __syncthreads();
        float s0 = 0.f, s1 = 0.f;
        #pragma unroll 16
        for (int d = 0; d < DD; ++d) {
            float qv = Qs[wq][d];
            s0 = fmaf(qv, Tl[d][lane],      s0);
            s1 = fmaf(qv, Tl[d][lane + 32], s1);
        }
        int qg = q0 + wq;
        S[wq][k0 + lane]      = (k0 + lane      <= qg) ? s0 : -INFINITY;
        S[wq][k0 + lane + 32] = (k0 + lane + 32 <= qg) ? s1 : -INFINITY;
    }
    __syncthreads();

    {
        int kmaxb = ntiles * 64;
        float m = -INFINITY;
        for (int kk = lane; kk < kmaxb; kk += 32) m = fmaxf(m, S[wq][kk]);
        #pragma unroll
        for (int o = 16; o; o >>= 1) m = fmaxf(m, __shfl_xor_sync(0xffffffffu, m, o));
        float sum = 0.f;
        for (int kk = lane; kk < kmaxb; kk += 32) {
            float e = __expf(S[wq][kk] - m);
            S[wq][kk] = e;
            sum += e;
        }
        #pragma unroll
        for (int o = 16; o; o >>= 1) sum += __shfl_xor_sync(0xffffffffu, sum, o);
        float inv = 1.f / sum;
        for (int kk = lane; kk < kmaxb; kk += 32) S[wq][kk] *= inv;
    }
    __syncthreads();

    float y0 = 0.f, y1 = 0.f;
    for (int kt = 0; kt < ntiles; ++kt) {
        int k0 = kt * 64;
        for (int f = tid; f < 64 * 16; f += 256) {
            int kk = f >> 4, c4 = (f & 15) * 4;
            float4 vv = *(const float4*)(v + (baseRow + k0 + kk) * QKVW + c4);
            *(float4*)&Tl[kk][c4] = vv;
        }
        __syncthreads();
        #pragma unroll 16
        for (int kk = 0; kk < 64; ++kk) {
            float p = S[wq][k0 + kk];
            y0 = fmaf(p, Tl[kk][lane],      y0);
            y1 = fmaf(p, Tl[kk][lane + 32], y1);
        }
        __syncthreads();
    }
    size_t o0 = (baseRow + q0 + wq) * EE + colOff + lane;
    __nv_bfloat16 h0, l0, h1, l1;
    split_bf16(y0, h0, l0);
    split_bf16(y1, h1, l1);
    yh[o0]      = h0; yl[o0]      = l0;
    yh[o0 + 32] = h1; yl[o0 + 32] = l1;
}

// ---------------------------------------------------------------------------
// Launch
// ---------------------------------------------------------------------------
extern "C" void kernel_launch(void* const* d_in, const int* in_sizes, int n_in,
                              void* d_out, int out_size)
{
    const int*   x     = (const int*)  d_in[0];
    const float* tok   = (const float*)d_in[2];
    const float* pos   = (const float*)d_in[3];
    const float* ln1g  = (const float*)d_in[4];
    const float* ln1b  = (const float*)d_in[5];
    const float* Wq    = (const float*)d_in[6];
    const float* bq    = (const float*)d_in[7];
    const float* Wk    = (const float*)d_in[8];
    const float* bk    = (const float*)d_in[9];
    const float* Wv    = (const float*)d_in[10];
    const float* bv    = (const float*)d_in[11];
    const float* Wp    = (const float*)d_in[12];
    const float* bp    = (const float*)d_in[13];
    const float* ln2g  = (const float*)d_in[14];
    const float* ln2b  = (const float*)d_in[15];
    const float* Wf1   = (const float*)d_in[16];
    const float* bf1   = (const float*)d_in[17];
    const float* Wf2   = (const float*)d_in[18];
    const float* bf2   = (const float*)d_in[19];
    const float* lnfg  = (const float*)d_in[20];
    const float* lnfb  = (const float*)d_in[21];
    const float* headw = (const float*)d_in[22];
    float* out = (float*)d_out;

    float *h, *qkv, *bqkv;
    cudaGetSymbolAddress((void**)&h,    g_h);
    cudaGetSymbolAddress((void**)&qkv,  g_qkv);
    cudaGetSymbolAddress((void**)&bqkv, g_bqkv);
    __nv_bfloat16 *xnh, *xnl, *yh, *yl, *mh, *ml;
    cudaGetSymbolAddress((void**)&xnh, g_xn_h);
    cudaGetSymbolAddress((void**)&xnl, g_xn_l);
    cudaGetSymbolAddress((void**)&yh,  g_y_h);
    cudaGetSymbolAddress((void**)&yl,  g_y_l);
    cudaGetSymbolAddress((void**)&mh,  g_mlp_h);
    cudaGetSymbolAddress((void**)&ml,  g_mlp_l);
    __nv_bfloat16 *wqkvh, *wqkvl, *wph, *wpl;
    __nv_bfloat16 *f1h, *f1l, *f2h, *f2l, *hdh, *hdl;
    cudaGetSymbolAddress((void**)&wqkvh, g_wqkvT_h);
    cudaGetSymbolAddress((void**)&wqkvl, g_wqkvT_l);
    cudaGetSymbolAddress((void**)&wph, g_wpT_h); cudaGetSymbolAddress((void**)&wpl, g_wpT_l);
    cudaGetSymbolAddress((void**)&f1h, g_f1T_h); cudaGetSymbolAddress((void**)&f1l, g_f1T_l);
    cudaGetSymbolAddress((void**)&f2h, g_f2T_h); cudaGetSymbolAddress((void**)&f2l, g_f2T_l);
    cudaGetSymbolAddress((void**)&hdh, g_hdT_h); cudaGetSymbolAddress((void**)&hdl, g_hdT_l);

    cudaFuncSetAttribute(mma_gemm, cudaFuncAttributeMaxDynamicSharedMemorySize, GEMM_SMEM);

    // --- weight convert + transpose (QKV packed into [3072][1024] rows) ---
    const size_t QLS = (size_t)QKVW * EE;
    dim3 wb(32, 8);
    wconv_kernel<<<dim3(EE / 32, EE / 32, LL), wb>>>(Wq, wqkvh + 0 * EE * EE,
                                                     wqkvl + 0 * EE * EE, EE, EE, QLS);
    wconv_kernel<<<dim3(EE / 32, EE / 32, LL), wb>>>(Wk, wqkvh + 1 * (size_t)EE * EE,
                                                     wqkvl + 1 * (size_t)EE * EE, EE, EE, QLS);
    wconv_kernel<<<dim3(EE / 32, EE / 32, LL), wb>>>(Wv, wqkvh + 2 * (size_t)EE * EE,
                                                     wqkvl + 2 * (size_t)EE * EE, EE, EE, QLS);
    wconv_kernel<<<dim3(EE / 32, EE / 32, LL), wb>>>(Wp,  wph, wpl, EE, EE, (size_t)EE * EE);
    wconv_kernel<<<dim3(FF / 32, EE / 32, LL), wb>>>(Wf1, f1h, f1l, EE, FF, (size_t)EE * FF);
    wconv_kernel<<<dim3(EE / 32, FF / 32, LL), wb>>>(Wf2, f2h, f2l, FF, EE, (size_t)EE * FF);
    wconv_kernel<<<dim3(VV / 32, EE / 32, 1 ), wb>>>(headw, hdh, hdl, EE, VV, (size_t)EE * VV);
    packb_kernel<<<LL * 3, EE>>>(bq, bk, bv, bqkv);

    embed_kernel<<<MR, 256>>>(x, tok, pos, h);

    dim3 gQKV(QKVW / 256, MR / 128);
    dim3 gE  (EE   / 256, MR / 128);
    dim3 gF  (FF   / 256, MR / 128);
    dim3 gHd (VV   / 256, MR / 128);

    for (int l = 0; l < LL; ++l) {
        size_t oE  = (size_t)l * EE;
        size_t oQ  = (size_t)l * QKVW;
        size_t oQW = (size_t)l * QLS;
        size_t oEE = (size_t)l * EE * EE;
        size_t oF  = (size_t)l * FF;
        size_t oEF = (size_t)l * EE * FF;

        ln_kernel<<<MR, 256>>>(h, ln1g + oE, ln1b + oE, xnh, xnl);

        // qkv = xn @ Wqkv + bqkv   (fused, N=3072)
        mma_gemm<<<gQKV, 256, GEMM_SMEM>>>(xnh, xnl, wqkvh + oQW, wqkvl + oQW,
                                           bqkv + oQ, nullptr, qkv, nullptr, nullptr,
                                           MR, QKVW, EE, 0);

        attn_kernel<<<BB * HH * (TT / AQ), 256>>>(qkv, yh, yl);

        // h = h + y @ Wp + bp
        mma_gemm<<<gE, 256, GEMM_SMEM>>>(yh, yl, wph + oEE, wpl + oEE,
                                         bp + oE, h, h, nullptr, nullptr,
                                         MR, EE, EE, 0);

        ln_kernel<<<MR, 256>>>(h, ln2g + oE, ln2b + oE, xnh, xnl);

        // mlp = gelu(xn @ Wf1 + bf1)  -> bf16 hi/lo
        mma_gemm<<<gF, 256, GEMM_SMEM>>>(xnh, xnl, f1h + oEF, f1l + oEF,
                                         bf1 + oF, nullptr, nullptr, mh, ml,
                                         MR, FF, EE, 1);

        // h = h + mlp @ Wf2 + bf2
        mma_gemm<<<gE, 256, GEMM_SMEM>>>(mh, ml, f2h + oEF, f2l + oEF,
                                         bf2 + oE, h, h, nullptr, nullptr,
                                         MR, EE, FF, 0);
    }

    ln_kernel<<<MR, 256>>>(h, lnfg, lnfb, xnh, xnl);
    mma_gemm<<<gHd, 256, GEMM_SMEM>>>(xnh, xnl, hdh, hdl,
                                      nullptr, nullptr, out, nullptr, nullptr,
                                      MR, VV, EE, 0);
}